// round 11
// baseline (speedup 1.0000x reference)
#include <cuda_runtime.h>
#include <cstdint>

// ---------------------------------------------------------------------------
// DOMINANT 4-layer GCN autoencoder.
// Norm-factored: Hs = (X@W)*dis_row  =>  out[d] = dis_d*(sum Hs[src] + Hs[d]) + b
// Edge slots carry ONLY src (4B). CSR gather aggregation + FFMA2 GEMMs, with
// agg->GEMM FUSION: a block aggregates its own row range straight into the
// GEMM's smem operand (no global round trip, no extra launch).
// gemm1 overlaps graph prep on a second stream (dis computed inline).
//   L1: Hs1=x@W1*dis                      -> hbuf    (side stream)
//   F12: agg(hbuf)+b1,relu  ==> gemm W2*dis -> abuf
//   F23: agg(abuf)+b2,relu  ==> z (global) + gemm W3*dis -> hbuf
//   A3:  agg(hbuf)+b3,relu,*dis -> abuf
//   F4:  agg(abuf)          ==> gemm W4+b4 -> xhat     (A(XW) == (AX)W)
//   out = concat(x_hat[N,128], z[N,64])
// ---------------------------------------------------------------------------

#define MAXN 50048
#define MAXE 640000

__device__ float g_h[(size_t)MAXN * 64];    // scaled post-GEMM features
__device__ float g_buf[(size_t)MAXN * 64];  // ping-pong buffer
__device__ float g_dis[MAXN];               // rsqrt(deg+1)
__device__ int   g_deg[MAXN];               // in-degree (edges only)
__device__ int   g_off[MAXN];               // CSR slot base per node
__device__ int   g_cur[MAXN];               // scatter cursors (pre-init to off)
__device__ int2  g_sd[MAXE];                // decoded (src, dst)
__device__ int   g_esrc[MAXE];              // CSR slot: src only
__device__ int   g_flag;                    // 1 => edge_index is int32
__device__ int   g_total;                   // global slot allocator

// ========================= graph prep kernels ==============================
__global__ void detect_zero_kernel(const long long* __restrict__ p, int cnt, int n) {
    int i = blockIdx.x * blockDim.x + threadIdx.x;
    if (i < n) g_deg[i] = 0;
    if (i == 0) g_total = 0;
    if (blockIdx.x == 0) {
        __shared__ int bad;
        if (threadIdx.x == 0) bad = 0;
        __syncthreads();
        int lb = 0;
        for (int j = threadIdx.x; j < cnt; j += blockDim.x) {
            long long v = p[j];
            if (v < 0 || v > 0x7fffffffLL) lb = 1;
        }
        if (lb) atomicOr(&bad, 1);
        __syncthreads();
        if (threadIdx.x == 0) g_flag = bad;
    }
}

__global__ void decode_count_kernel(const void* __restrict__ ei, int E) {
    int e = blockIdx.x * blockDim.x + threadIdx.x;
    if (e >= E) return;
    int s, d;
    if (g_flag) {
        const int* p = (const int*)ei;
        s = p[e]; d = p[E + e];
    } else {
        const long long* p = (const long long*)ei;
        s = (int)p[e]; d = (int)p[(size_t)E + e];
    }
    g_sd[e] = make_int2(s, d);
    atomicAdd(&g_deg[d], 1);
}

// g_dis = rsqrt(deg+1); block scan of deg; base from global allocator
// (node ranges disjoint, arbitrary order). Cursors pre-init to base.
__global__ void dis_off_kernel(int n) {
    __shared__ int sh[256];
    __shared__ int base;
    int i = blockIdx.x * 256 + threadIdx.x;
    int v = 0;
    if (i < n) {
        v = g_deg[i];
        g_dis[i] = rsqrtf((float)(v + 1));
    }
    sh[threadIdx.x] = v;
    __syncthreads();
#pragma unroll
    for (int ofs = 1; ofs < 256; ofs <<= 1) {
        int t = (threadIdx.x >= ofs) ? sh[threadIdx.x - ofs] : 0;
        __syncthreads();
        sh[threadIdx.x] += t;
        __syncthreads();
    }
    if (threadIdx.x == 255) base = atomicAdd(&g_total, sh[255]);
    __syncthreads();
    if (i < n) {
        int o = base + sh[threadIdx.x] - v;
        g_off[i] = o;
        g_cur[i] = o;
    }
}

__global__ void csr_scatter_kernel(int E) {
    int e = blockIdx.x * blockDim.x + threadIdx.x;
    if (e >= E) return;
    int2 sd = g_sd[e];
    int pos = atomicAdd(&g_cur[sd.y], 1);
    g_esrc[pos] = sd.x;
}

// ========================= helpers ========================================
__device__ __forceinline__ float4 agg_node(const float4* __restrict__ H4,
                                           int node, int c) {
    float4 acc = H4[(size_t)node * 16 + c];   // self term
    int e = g_off[node];
    int end = e + g_deg[node];
    for (; e + 3 < end; e += 4) {
        int s0 = g_esrc[e];
        int s1 = g_esrc[e + 1];
        int s2 = g_esrc[e + 2];
        int s3 = g_esrc[e + 3];
        float4 h0 = H4[(size_t)s0 * 16 + c];
        float4 h1 = H4[(size_t)s1 * 16 + c];
        float4 h2 = H4[(size_t)s2 * 16 + c];
        float4 h3 = H4[(size_t)s3 * 16 + c];
        acc.x += h0.x; acc.y += h0.y; acc.z += h0.z; acc.w += h0.w;
        acc.x += h1.x; acc.y += h1.y; acc.z += h1.z; acc.w += h1.w;
        acc.x += h2.x; acc.y += h2.y; acc.z += h2.z; acc.w += h2.w;
        acc.x += h3.x; acc.y += h3.y; acc.z += h3.z; acc.w += h3.w;
    }
    if (e + 1 < end) {
        int s0 = g_esrc[e];
        int s1 = g_esrc[e + 1];
        float4 h0 = H4[(size_t)s0 * 16 + c];
        float4 h1 = H4[(size_t)s1 * 16 + c];
        acc.x += h0.x; acc.y += h0.y; acc.z += h0.z; acc.w += h0.w;
        acc.x += h1.x; acc.y += h1.y; acc.z += h1.z; acc.w += h1.w;
        e += 2;
    }
    if (e < end) {
        int s0 = g_esrc[e];
        float4 h0 = H4[(size_t)s0 * 16 + c];
        acc.x += h0.x; acc.y += h0.y; acc.z += h0.z; acc.w += h0.w;
    }
    return acc;
}

// ===================== gemm1 (standalone, overlapped) ======================
// Hs1[n,64] = (x[n,128] @ W1) * rsqrt(deg+1)  — dis computed inline so this
// only depends on g_deg (runs concurrently with dis_off + csr_scatter).
template <int K, int DOUT, int R>
__global__ __launch_bounds__(256) void gemm1_kernel(
    const float* __restrict__ X, const float* __restrict__ W,
    float* __restrict__ Y, int n)
{
    constexpr int CG = DOUT / 4;
    constexpr int RG = 256 / CG;
    constexpr int ROWS = RG * R;

    extern __shared__ char dyn[];
    float* Ws = (float*)dyn;
    unsigned long long* Xs2 = (unsigned long long*)(dyn + (size_t)K * DOUT * 4);

    const int t = threadIdx.x;
    const int row0 = blockIdx.x * ROWS;

    for (int i = t; i < K * DOUT / 4; i += 256)
        ((float4*)Ws)[i] = ((const float4*)W)[i];

    for (int i = t; i < ROWS * K / 4; i += 256) {
        int pos = i * 4;
        int r = pos / K;
        int k = pos % K;
        int gr = row0 + r;
        float4 v = make_float4(0.f, 0.f, 0.f, 0.f);
        if (gr < n) v = *(const float4*)&X[(size_t)gr * K + k];
        unsigned long long d0, d1, d2, d3;
        asm("mov.b64 %0, {%1, %1};" : "=l"(d0) : "f"(v.x));
        asm("mov.b64 %0, {%1, %1};" : "=l"(d1) : "f"(v.y));
        asm("mov.b64 %0, {%1, %1};" : "=l"(d2) : "f"(v.z));
        asm("mov.b64 %0, {%1, %1};" : "=l"(d3) : "f"(v.w));
        unsigned long long* p = &Xs2[r * K + k];
        p[0] = d0; p[1] = d1; p[2] = d2; p[3] = d3;
    }
    __syncthreads();

    const int cg = t % CG;
    const int rg = t / CG;

    unsigned long long acc[R][2];
#pragma unroll
    for (int r = 0; r < R; r++) { acc[r][0] = 0ull; acc[r][1] = 0ull; }

#pragma unroll 4
    for (int k = 0; k < K; k++) {
        ulonglong2 w = *(const ulonglong2*)&Ws[k * DOUT + cg * 4];
#pragma unroll
        for (int r = 0; r < R; r++) {
            unsigned long long x2 = Xs2[(rg * R + r) * K + k];
            asm("fma.rn.f32x2 %0, %1, %2, %0;" : "+l"(acc[r][0]) : "l"(x2), "l"(w.x));
            asm("fma.rn.f32x2 %0, %1, %2, %0;" : "+l"(acc[r][1]) : "l"(x2), "l"(w.y));
        }
    }

#pragma unroll
    for (int r = 0; r < R; r++) {
        int gr = row0 + rg * R + r;
        if (gr < n) {
            float o0, o1, o2, o3;
            asm("mov.b64 {%0, %1}, %2;" : "=f"(o0), "=f"(o1) : "l"(acc[r][0]));
            asm("mov.b64 {%0, %1}, %2;" : "=f"(o2), "=f"(o3) : "l"(acc[r][1]));
            float sc = rsqrtf((float)(g_deg[gr] + 1));
            *(float4*)&Y[(size_t)gr * DOUT + cg * 4] =
                make_float4(o0 * sc, o1 * sc, o2 * sc, o3 * sc);
        }
    }
}

// ===================== fused agg + GEMM ====================================
// Block aggregates its ROWS nodes (16 thr/node, ROWS/16 passes) directly into
// the GEMM Xs2 operand (duplicated f32x2), then runs the GEMM. K fixed = 64.
// Agg result r = relu?(dis*acc + agg_b?); optional global write (for z).
// GEMM: Y = Xs2 @ W (+gemm_b) (*dis_row if GSCALE).
template <int DOUT, int R, bool ABIAS, bool ARELU, bool AWRITE,
          bool GBIAS, bool GSCALE>
__global__ __launch_bounds__(256) void fused_agg_gemm_kernel(
    const float* __restrict__ H, const float* __restrict__ agg_b,
    float* __restrict__ agg_out,
    const float* __restrict__ W, const float* __restrict__ gemm_b,
    float* __restrict__ Y, int n)
{
    constexpr int K = 64;
    constexpr int CG = DOUT / 4;
    constexpr int RG = 256 / CG;
    constexpr int ROWS = RG * R;

    extern __shared__ char dyn[];
    float* Ws = (float*)dyn;                                  // K*DOUT floats
    unsigned long long* Xs2 = (unsigned long long*)(dyn + (size_t)K * DOUT * 4);

    const int t = threadIdx.x;
    const int row0 = blockIdx.x * ROWS;
    const float4* H4 = (const float4*)H;

    for (int i = t; i < K * DOUT / 4; i += 256)
        ((float4*)Ws)[i] = ((const float4*)W)[i];

    // --- agg phase: ROWS/16 passes of 16 nodes x 16 columns ---
    const int c = t & 15;
#pragma unroll
    for (int pass = 0; pass < ROWS / 16; pass++) {
        int lrow = pass * 16 + (t >> 4);
        int node = row0 + lrow;
        float4 r = make_float4(0.f, 0.f, 0.f, 0.f);
        if (node < n) {
            float dis = g_dis[node];
            float4 acc = agg_node(H4, node, c);
            r.x = acc.x * dis; r.y = acc.y * dis;
            r.z = acc.z * dis; r.w = acc.w * dis;
            if (ABIAS) {
                float4 bb = *(const float4*)&agg_b[c * 4];
                r.x += bb.x; r.y += bb.y; r.z += bb.z; r.w += bb.w;
            }
            if (ARELU) {
                r.x = fmaxf(r.x, 0.f); r.y = fmaxf(r.y, 0.f);
                r.z = fmaxf(r.z, 0.f); r.w = fmaxf(r.w, 0.f);
            }
            if (AWRITE)
                ((float4*)agg_out)[(size_t)node * 16 + c] = r;
        }
        unsigned long long d0, d1, d2, d3;
        asm("mov.b64 %0, {%1, %1};" : "=l"(d0) : "f"(r.x));
        asm("mov.b64 %0, {%1, %1};" : "=l"(d1) : "f"(r.y));
        asm("mov.b64 %0, {%1, %1};" : "=l"(d2) : "f"(r.z));
        asm("mov.b64 %0, {%1, %1};" : "=l"(d3) : "f"(r.w));
        unsigned long long* p = &Xs2[lrow * K + c * 4];
        p[0] = d0; p[1] = d1; p[2] = d2; p[3] = d3;
    }
    __syncthreads();

    // --- GEMM phase ---
    const int cg = t % CG;
    const int rg = t / CG;

    unsigned long long acc[R][2];
#pragma unroll
    for (int r = 0; r < R; r++) { acc[r][0] = 0ull; acc[r][1] = 0ull; }

#pragma unroll 4
    for (int k = 0; k < K; k++) {
        ulonglong2 w = *(const ulonglong2*)&Ws[k * DOUT + cg * 4];
#pragma unroll
        for (int r = 0; r < R; r++) {
            unsigned long long x2 = Xs2[(rg * R + r) * K + k];
            asm("fma.rn.f32x2 %0, %1, %2, %0;" : "+l"(acc[r][0]) : "l"(x2), "l"(w.x));
            asm("fma.rn.f32x2 %0, %1, %2, %0;" : "+l"(acc[r][1]) : "l"(x2), "l"(w.y));
        }
    }

    float4 bb = make_float4(0.f, 0.f, 0.f, 0.f);
    if (GBIAS) bb = *(const float4*)&gemm_b[cg * 4];

#pragma unroll
    for (int r = 0; r < R; r++) {
        int gr = row0 + rg * R + r;
        if (gr < n) {
            float o0, o1, o2, o3;
            asm("mov.b64 {%0, %1}, %2;" : "=f"(o0), "=f"(o1) : "l"(acc[r][0]));
            asm("mov.b64 {%0, %1}, %2;" : "=f"(o2), "=f"(o3) : "l"(acc[r][1]));
            float sc = GSCALE ? g_dis[gr] : 1.0f;
            *(float4*)&Y[(size_t)gr * DOUT + cg * 4] =
                make_float4(o0 * sc + bb.x, o1 * sc + bb.y,
                            o2 * sc + bb.z, o3 * sc + bb.w);
        }
    }
}

// ===================== standalone agg (layer 3) ============================
// out = relu(dis*acc + b) * dis   (pre-scaled so L4 agg needs no src scale)
__global__ __launch_bounds__(256) void agg3_kernel(
    const float* __restrict__ H, const float* __restrict__ b,
    float* __restrict__ out, int n)
{
    int node = blockIdx.x * 16 + (threadIdx.x >> 4);
    int c = threadIdx.x & 15;
    if (node >= n) return;
    const float4* H4 = (const float4*)H;
    float dis = g_dis[node];
    float4 acc = agg_node(H4, node, c);
    float4 bb = *(const float4*)&b[c * 4];
    float4 r;
    r.x = fmaxf(acc.x * dis + bb.x, 0.f) * dis;
    r.y = fmaxf(acc.y * dis + bb.y, 0.f) * dis;
    r.z = fmaxf(acc.z * dis + bb.z, 0.f) * dis;
    r.w = fmaxf(acc.w * dis + bb.w, 0.f) * dis;
    ((float4*)out)[(size_t)node * 16 + c] = r;
}

static inline int ceil_div(long long a, int bsz) { return (int)((a + bsz - 1) / bsz); }

extern "C" void kernel_launch(void* const* d_in, const int* in_sizes, int n_in,
                              void* d_out, int out_size)
{
    const float* x  = (const float*)d_in[0];
    const void*  ei = d_in[1];
    const float* W1 = (const float*)d_in[2];
    const float* b1 = (const float*)d_in[3];
    const float* W2 = (const float*)d_in[4];
    const float* b2 = (const float*)d_in[5];
    const float* W3 = (const float*)d_in[6];
    const float* b3 = (const float*)d_in[7];
    const float* W4 = (const float*)d_in[8];
    const float* b4 = (const float*)d_in[9];

    const int N = in_sizes[0] / 128;
    const int E = in_sizes[1] / 2;

    float* out  = (float*)d_out;
    float* xhat = out;                       // [N,128]
    float* z    = out + (size_t)N * 128;     // [N,64]

    float* hbuf;  cudaGetSymbolAddress((void**)&hbuf, g_h);
    float* abuf;  cudaGetSymbolAddress((void**)&abuf, g_buf);

    const int SM_G1 = 128 * 64 * 4 + 64 * 128 * 8;   // 96K  (gemm1)
    const int SM_F2 = 64 * 64 * 4 + 64 * 64 * 8;     // 48K  (fused DOUT=64)
    const int SM_F4 = 64 * 128 * 4 + 32 * 64 * 8;    // 48K  (fused DOUT=128)

    static cudaStream_t s2 = nullptr;
    static cudaEvent_t ev_decode = nullptr, ev_gemm1 = nullptr;
    static bool init_done = false;
    if (!init_done) {
        cudaFuncSetAttribute(gemm1_kernel<128, 64, 4>,
                             cudaFuncAttributeMaxDynamicSharedMemorySize, SM_G1);
        cudaFuncSetAttribute(
            fused_agg_gemm_kernel<64, 4, true, true, false, false, true>,
            cudaFuncAttributeMaxDynamicSharedMemorySize, SM_F2);
        cudaFuncSetAttribute(
            fused_agg_gemm_kernel<64, 4, true, true, true, false, true>,
            cudaFuncAttributeMaxDynamicSharedMemorySize, SM_F2);
        cudaFuncSetAttribute(
            fused_agg_gemm_kernel<128, 4, false, false, false, true, false>,
            cudaFuncAttributeMaxDynamicSharedMemorySize, SM_F4);
        cudaStreamCreateWithFlags(&s2, cudaStreamNonBlocking);
        cudaEventCreateWithFlags(&ev_decode, cudaEventDisableTiming);
        cudaEventCreateWithFlags(&ev_gemm1, cudaEventDisableTiming);
        init_done = true;
    }

    const int nb = ceil_div(N, 256);

    // --- prep head (main stream) ---
    detect_zero_kernel<<<nb, 256>>>((const long long*)ei, 4096, N);
    decode_count_kernel<<<ceil_div(E, 256), 256>>>(ei, E);
    cudaEventRecord(ev_decode, 0);

    // --- gemm1 on side stream, overlapped with dis_off + csr_scatter ---
    cudaStreamWaitEvent(s2, ev_decode, 0);
    gemm1_kernel<128, 64, 4><<<ceil_div(N, 64), 256, SM_G1, s2>>>(x, W1, hbuf, N);
    cudaEventRecord(ev_gemm1, s2);

    dis_off_kernel<<<nb, 256>>>(N);
    csr_scatter_kernel<<<ceil_div(E, 256), 256>>>(E);
    cudaStreamWaitEvent(0, ev_gemm1, 0);

    // --- F12: agg(hbuf)+b1,relu ==> gemm2 *dis -> abuf ---
    fused_agg_gemm_kernel<64, 4, true, true, false, false, true>
        <<<ceil_div(N, 64), 256, SM_F2>>>(hbuf, b1, nullptr, W2, nullptr, abuf, N);

    // --- F23: agg(abuf)+b2,relu ==> z + gemm3 *dis -> hbuf ---
    fused_agg_gemm_kernel<64, 4, true, true, true, false, true>
        <<<ceil_div(N, 64), 256, SM_F2>>>(abuf, b2, z, W3, nullptr, hbuf, N);

    // --- A3: abuf = relu(dis*agg(hbuf) + b3) * dis ---
    agg3_kernel<<<ceil_div(N, 16), 256>>>(hbuf, b3, abuf, N);

    // --- F4: agg(abuf) ==> gemm4 + b4 -> xhat ---
    fused_agg_gemm_kernel<128, 4, false, false, false, true, false>
        <<<ceil_div(N, 32), 256, SM_F4>>>(abuf, nullptr, nullptr, W4, b4, xhat, N);
}

// round 12
// speedup vs baseline: 1.0976x; 1.0976x over previous
#include <cuda_runtime.h>
#include <cuda_fp16.h>
#include <cstdint>

// ---------------------------------------------------------------------------
// DOMINANT 4-layer GCN autoencoder.
// Norm-factored: Hs = (X@W)*dis_row  =>  out[d] = dis_d*(sum Hs[src] + Hs[d]) + b
// Gather-target features stored in FP16 (halves aggregation L2 traffic);
// all accumulation fp32. CSR gather (16 thr/node, 4-deep unroll, no hot-path
// atomics) + packed-f32x2 (FFMA2) GEMMs. gemm1 overlaps graph prep on a
// second stream (dis computed inline from g_deg).
//   gemm1: x@W1*dis -> HH(fp16)          (side stream)
//   agg1:  gather HH, +b1, relu          -> fbuf (fp32)
//   gemm2: fbuf@W2*dis -> HH(fp16)
//   agg2:  gather HH, +b2, relu          -> z (fp32, output)
//   gemm3: z@W3*dis -> HH(fp16)
//   agg3:  gather HH, +b3, relu, *dis    -> BH (fp16)
//   agg4:  gather BH                     -> fbuf (fp32)
//   gemm4: fbuf@W4 + b4 -> x_hat             (A(XW) == (AX)W)
//   out = concat(x_hat[N,128], z[N,64])
// ---------------------------------------------------------------------------

#define MAXN 50048
#define MAXE 640000

__device__ uint2 g_hh[(size_t)MAXN * 16];   // fp16 features (64 halves/row)
__device__ uint2 g_bh[(size_t)MAXN * 16];   // fp16 agg3 output
__device__ float g_fbuf[(size_t)MAXN * 64]; // fp32 scratch (agg1/agg4 out)
__device__ float g_dis[MAXN];               // rsqrt(deg+1)
__device__ int   g_deg[MAXN];               // in-degree (edges only)
__device__ int   g_off[MAXN];               // CSR slot base per node
__device__ int   g_cur[MAXN];               // scatter cursors (pre-init to off)
__device__ int2  g_sd[MAXE];                // decoded (src, dst)
__device__ int   g_esrc[MAXE];              // CSR slot: src only
__device__ int   g_flag;                    // 1 => edge_index is int32
__device__ int   g_total;                   // global slot allocator

// ========================= graph prep kernels ==============================
__global__ void detect_zero_kernel(const long long* __restrict__ p, int cnt, int n) {
    int i = blockIdx.x * blockDim.x + threadIdx.x;
    if (i < n) g_deg[i] = 0;
    if (i == 0) g_total = 0;
    if (blockIdx.x == 0) {
        __shared__ int bad;
        if (threadIdx.x == 0) bad = 0;
        __syncthreads();
        int lb = 0;
        for (int j = threadIdx.x; j < cnt; j += blockDim.x) {
            long long v = p[j];
            if (v < 0 || v > 0x7fffffffLL) lb = 1;
        }
        if (lb) atomicOr(&bad, 1);
        __syncthreads();
        if (threadIdx.x == 0) g_flag = bad;
    }
}

__global__ void decode_count_kernel(const void* __restrict__ ei, int E) {
    int e = blockIdx.x * blockDim.x + threadIdx.x;
    if (e >= E) return;
    int s, d;
    if (g_flag) {
        const int* p = (const int*)ei;
        s = p[e]; d = p[E + e];
    } else {
        const long long* p = (const long long*)ei;
        s = (int)p[e]; d = (int)p[(size_t)E + e];
    }
    g_sd[e] = make_int2(s, d);
    atomicAdd(&g_deg[d], 1);
}

__global__ void dis_off_kernel(int n) {
    __shared__ int sh[256];
    __shared__ int base;
    int i = blockIdx.x * 256 + threadIdx.x;
    int v = 0;
    if (i < n) {
        v = g_deg[i];
        g_dis[i] = rsqrtf((float)(v + 1));
    }
    sh[threadIdx.x] = v;
    __syncthreads();
#pragma unroll
    for (int ofs = 1; ofs < 256; ofs <<= 1) {
        int t = (threadIdx.x >= ofs) ? sh[threadIdx.x - ofs] : 0;
        __syncthreads();
        sh[threadIdx.x] += t;
        __syncthreads();
    }
    if (threadIdx.x == 255) base = atomicAdd(&g_total, sh[255]);
    __syncthreads();
    if (i < n) {
        int o = base + sh[threadIdx.x] - v;
        g_off[i] = o;
        g_cur[i] = o;
    }
}

__global__ void csr_scatter_kernel(int E) {
    int e = blockIdx.x * blockDim.x + threadIdx.x;
    if (e >= E) return;
    int2 sd = g_sd[e];
    int pos = atomicAdd(&g_cur[sd.y], 1);
    g_esrc[pos] = sd.x;
}

// ========================= helpers ========================================
__device__ __forceinline__ float4 h2f4(uint2 r) {
    __half2 a = *(__half2*)&r.x;
    __half2 b = *(__half2*)&r.y;
    float2 f0 = __half22float2(a);
    float2 f1 = __half22float2(b);
    return make_float4(f0.x, f0.y, f1.x, f1.y);
}
__device__ __forceinline__ uint2 f2h4(float4 v) {
    __half2 a = __float22half2_rn(make_float2(v.x, v.y));
    __half2 b = __float22half2_rn(make_float2(v.z, v.w));
    uint2 r;
    r.x = *(unsigned*)&a;
    r.y = *(unsigned*)&b;
    return r;
}

// fp16 row gather-accumulate for one node/column; acc in fp32
__device__ __forceinline__ float4 agg_node(const uint2* __restrict__ HH,
                                           int node, int c) {
    float4 acc = h2f4(HH[(size_t)node * 16 + c]);   // self term
    int e = g_off[node];
    int end = e + g_deg[node];
    for (; e + 3 < end; e += 4) {
        int s0 = g_esrc[e];
        int s1 = g_esrc[e + 1];
        int s2 = g_esrc[e + 2];
        int s3 = g_esrc[e + 3];
        float4 h0 = h2f4(HH[(size_t)s0 * 16 + c]);
        float4 h1 = h2f4(HH[(size_t)s1 * 16 + c]);
        float4 h2 = h2f4(HH[(size_t)s2 * 16 + c]);
        float4 h3 = h2f4(HH[(size_t)s3 * 16 + c]);
        acc.x += h0.x; acc.y += h0.y; acc.z += h0.z; acc.w += h0.w;
        acc.x += h1.x; acc.y += h1.y; acc.z += h1.z; acc.w += h1.w;
        acc.x += h2.x; acc.y += h2.y; acc.z += h2.z; acc.w += h2.w;
        acc.x += h3.x; acc.y += h3.y; acc.z += h3.z; acc.w += h3.w;
    }
    if (e + 1 < end) {
        int s0 = g_esrc[e];
        int s1 = g_esrc[e + 1];
        float4 h0 = h2f4(HH[(size_t)s0 * 16 + c]);
        float4 h1 = h2f4(HH[(size_t)s1 * 16 + c]);
        acc.x += h0.x; acc.y += h0.y; acc.z += h0.z; acc.w += h0.w;
        acc.x += h1.x; acc.y += h1.y; acc.z += h1.z; acc.w += h1.w;
        e += 2;
    }
    if (e < end) {
        int s0 = g_esrc[e];
        float4 h0 = h2f4(HH[(size_t)s0 * 16 + c]);
        acc.x += h0.x; acc.y += h0.y; acc.z += h0.z; acc.w += h0.w;
    }
    return acc;
}

// ===================== packed-f32x2 GEMM ===================================
// Y = X[n,K] @ W[K,DOUT] (+b) (*scale_row), output fp32 or fp16.
// SCALE_MODE: 0 none, 1 g_dis[row], 2 rsqrt(g_deg[row]+1) inline.
template <int K, int DOUT, int R, bool BIAS, int SCALE_MODE, bool HOUT>
__global__ __launch_bounds__(256) void gemm_kernel(
    const float* __restrict__ X, const float* __restrict__ W,
    const float* __restrict__ b, void* __restrict__ Y, int n)
{
    constexpr int CG = DOUT / 4;
    constexpr int RG = 256 / CG;
    constexpr int ROWS = RG * R;

    extern __shared__ char dyn[];
    float* Ws = (float*)dyn;                                  // K*DOUT floats
    unsigned long long* Xs2 = (unsigned long long*)(dyn + (size_t)K * DOUT * 4);

    const int t = threadIdx.x;
    const int row0 = blockIdx.x * ROWS;

    for (int i = t; i < K * DOUT / 4; i += 256)
        ((float4*)Ws)[i] = ((const float4*)W)[i];

    for (int i = t; i < ROWS * K / 4; i += 256) {
        int pos = i * 4;
        int r = pos / K;
        int k = pos % K;
        int gr = row0 + r;
        float4 v = make_float4(0.f, 0.f, 0.f, 0.f);
        if (gr < n) v = *(const float4*)&X[(size_t)gr * K + k];
        unsigned long long d0, d1, d2, d3;
        asm("mov.b64 %0, {%1, %1};" : "=l"(d0) : "f"(v.x));
        asm("mov.b64 %0, {%1, %1};" : "=l"(d1) : "f"(v.y));
        asm("mov.b64 %0, {%1, %1};" : "=l"(d2) : "f"(v.z));
        asm("mov.b64 %0, {%1, %1};" : "=l"(d3) : "f"(v.w));
        unsigned long long* p = &Xs2[r * K + k];
        p[0] = d0; p[1] = d1; p[2] = d2; p[3] = d3;
    }
    __syncthreads();

    const int cg = t % CG;
    const int rg = t / CG;

    unsigned long long acc[R][2];
#pragma unroll
    for (int r = 0; r < R; r++) { acc[r][0] = 0ull; acc[r][1] = 0ull; }

#pragma unroll 4
    for (int k = 0; k < K; k++) {
        ulonglong2 w = *(const ulonglong2*)&Ws[k * DOUT + cg * 4];
#pragma unroll
        for (int r = 0; r < R; r++) {
            unsigned long long x2 = Xs2[(rg * R + r) * K + k];
            asm("fma.rn.f32x2 %0, %1, %2, %0;" : "+l"(acc[r][0]) : "l"(x2), "l"(w.x));
            asm("fma.rn.f32x2 %0, %1, %2, %0;" : "+l"(acc[r][1]) : "l"(x2), "l"(w.y));
        }
    }

    float4 bb = make_float4(0.f, 0.f, 0.f, 0.f);
    if (BIAS) bb = *(const float4*)&b[cg * 4];

#pragma unroll
    for (int r = 0; r < R; r++) {
        int gr = row0 + rg * R + r;
        if (gr < n) {
            float o0, o1, o2, o3;
            asm("mov.b64 {%0, %1}, %2;" : "=f"(o0), "=f"(o1) : "l"(acc[r][0]));
            asm("mov.b64 {%0, %1}, %2;" : "=f"(o2), "=f"(o3) : "l"(acc[r][1]));
            float sc = 1.0f;
            if (SCALE_MODE == 1) sc = g_dis[gr];
            if (SCALE_MODE == 2) sc = rsqrtf((float)(g_deg[gr] + 1));
            float4 ov = make_float4(o0 * sc + bb.x, o1 * sc + bb.y,
                                    o2 * sc + bb.z, o3 * sc + bb.w);
            if (HOUT)
                ((uint2*)Y)[(size_t)gr * CG + cg] = f2h4(ov);
            else
                *(float4*)&((float*)Y)[(size_t)gr * DOUT + cg * 4] = ov;
        }
    }
}

// ===================== CSR gather aggregation ==============================
// 16 threads per node (4 columns each). r = (relu)(dis*acc (+b)) (*dis);
// output fp32 (float4) or fp16 (uint2).
template <bool BIAS, bool RELU, bool SCALE_OUT, bool HOUT>
__global__ __launch_bounds__(256) void agg_gather_kernel(
    const uint2* __restrict__ HH, const float* __restrict__ b,
    void* __restrict__ out, int n)
{
    int node = blockIdx.x * 16 + (threadIdx.x >> 4);
    int c = threadIdx.x & 15;
    if (node >= n) return;

    float dis = g_dis[node];
    float4 acc = agg_node(HH, node, c);

    float4 r;
    r.x = acc.x * dis; r.y = acc.y * dis;
    r.z = acc.z * dis; r.w = acc.w * dis;
    if (BIAS) {
        float4 bb = *(const float4*)&b[c * 4];
        r.x += bb.x; r.y += bb.y; r.z += bb.z; r.w += bb.w;
    }
    if (RELU) {
        r.x = fmaxf(r.x, 0.f); r.y = fmaxf(r.y, 0.f);
        r.z = fmaxf(r.z, 0.f); r.w = fmaxf(r.w, 0.f);
    }
    if (SCALE_OUT) {
        r.x *= dis; r.y *= dis; r.z *= dis; r.w *= dis;
    }
    if (HOUT)
        ((uint2*)out)[(size_t)node * 16 + c] = f2h4(r);
    else
        ((float4*)out)[(size_t)node * 16 + c] = r;
}

static inline int ceil_div(long long a, int bsz) { return (int)((a + bsz - 1) / bsz); }

extern "C" void kernel_launch(void* const* d_in, const int* in_sizes, int n_in,
                              void* d_out, int out_size)
{
    const float* x  = (const float*)d_in[0];
    const void*  ei = d_in[1];
    const float* W1 = (const float*)d_in[2];
    const float* b1 = (const float*)d_in[3];
    const float* W2 = (const float*)d_in[4];
    const float* b2 = (const float*)d_in[5];
    const float* W3 = (const float*)d_in[6];
    const float* b3 = (const float*)d_in[7];
    const float* W4 = (const float*)d_in[8];
    const float* b4 = (const float*)d_in[9];

    const int N = in_sizes[0] / 128;
    const int E = in_sizes[1] / 2;

    float* out  = (float*)d_out;
    float* xhat = out;                       // [N,128]
    float* z    = out + (size_t)N * 128;     // [N,64]

    uint2* hh;    cudaGetSymbolAddress((void**)&hh, g_hh);
    uint2* bh;    cudaGetSymbolAddress((void**)&bh, g_bh);
    float* fbuf;  cudaGetSymbolAddress((void**)&fbuf, g_fbuf);

    // dynamic smem: Ws (K*DOUT*4) + Xs2 (ROWS*K*8)
    const int SM_G1 = 128 * 64 * 4 + 64 * 128 * 8;   // 96K
    const int SM_G2 = 64 * 64 * 4 + 64 * 64 * 8;     // 48K
    const int SM_G4 = 64 * 128 * 4 + 32 * 64 * 8;    // 48K

    static cudaStream_t s2 = nullptr;
    static cudaEvent_t ev_decode = nullptr, ev_gemm1 = nullptr;
    static bool init_done = false;
    if (!init_done) {
        cudaFuncSetAttribute(gemm_kernel<128, 64, 4, false, 2, true>,
                             cudaFuncAttributeMaxDynamicSharedMemorySize, SM_G1);
        cudaFuncSetAttribute(gemm_kernel<64, 64, 4, false, 1, true>,
                             cudaFuncAttributeMaxDynamicSharedMemorySize, SM_G2);
        cudaFuncSetAttribute(gemm_kernel<64, 128, 4, true, 0, false>,
                             cudaFuncAttributeMaxDynamicSharedMemorySize, SM_G4);
        cudaStreamCreateWithFlags(&s2, cudaStreamNonBlocking);
        cudaEventCreateWithFlags(&ev_decode, cudaEventDisableTiming);
        cudaEventCreateWithFlags(&ev_gemm1, cudaEventDisableTiming);
        init_done = true;
    }

    const int nb = ceil_div(N, 256);
    const int ab = ceil_div(N, 16);          // agg: 16 nodes per 256-thr block

    // --- prep head (main stream) ---
    detect_zero_kernel<<<nb, 256>>>((const long long*)ei, 4096, N);
    decode_count_kernel<<<ceil_div(E, 256), 256>>>(ei, E);
    cudaEventRecord(ev_decode, 0);

    // --- gemm1 on side stream (needs only g_deg + x + W1), overlapped with
    //     dis_off + csr_scatter on the main stream ---
    cudaStreamWaitEvent(s2, ev_decode, 0);
    gemm_kernel<128, 64, 4, false, 2, true><<<ceil_div(N, 64), 256, SM_G1, s2>>>(
        x, W1, nullptr, hh, N);
    cudaEventRecord(ev_gemm1, s2);

    dis_off_kernel<<<nb, 256>>>(N);
    csr_scatter_kernel<<<ceil_div(E, 256), 256>>>(E);
    cudaStreamWaitEvent(0, ev_gemm1, 0);

    // --- layer 1 agg: fbuf = relu(dis*agg(hh) + b1)  (fp32) ---
    agg_gather_kernel<true, true, false, false><<<ab, 256>>>(hh, b1, fbuf, N);

    // --- layer 2: hh = (fbuf@W2)*dis (fp16); z = relu(dis*agg + b2) ---
    gemm_kernel<64, 64, 4, false, 1, true><<<ceil_div(N, 64), 256, SM_G2>>>(
        fbuf, W2, nullptr, hh, N);
    agg_gather_kernel<true, true, false, false><<<ab, 256>>>(hh, b2, z, N);

    // --- layer 3: hh = (z@W3)*dis (fp16); bh = relu(dis*agg + b3)*dis (fp16) ---
    gemm_kernel<64, 64, 4, false, 1, true><<<ceil_div(N, 64), 256, SM_G2>>>(
        z, W3, nullptr, hh, N);
    agg_gather_kernel<true, true, true, true><<<ab, 256>>>(hh, b3, bh, N);

    // --- layer 4: fbuf = dis*agg(bh) (fp32); x_hat = fbuf@W4 + b4 ---
    agg_gather_kernel<false, false, false, false><<<ab, 256>>>(bh, nullptr, fbuf, N);
    gemm_kernel<64, 128, 4, true, 0, false><<<ceil_div(N, 32), 256, SM_G4>>>(
        fbuf, W4, b4, xhat, N);
}